// round 12
// baseline (speedup 1.0000x reference)
#include <cuda_runtime.h>
#include <cuda_bf16.h>
#include <math.h>
#include <cstdint>

#define S_LEN 4096
#define D_MODEL 1024

// ============================ PTX helpers (sm_80-class only) ===============
__device__ __forceinline__ uint32_t smem_u32(const void* p) {
    uint32_t a;
    asm("{ .reg .u64 t; cvta.to.shared.u64 t, %1; cvt.u32.u64 %0, t; }"
        : "=r"(a) : "l"(p));
    return a;
}

__device__ __forceinline__ void cp_async16(uint32_t smem_addr, const void* gptr) {
    asm volatile("cp.async.cg.shared.global [%0], [%1], 16;"
                 :: "r"(smem_addr), "l"(gptr));
}
#define CP_COMMIT() asm volatile("cp.async.commit_group;" ::: "memory")
template<int N> __device__ __forceinline__ void cp_wait() {
    asm volatile("cp.async.wait_group %0;" :: "n"(N) : "memory");
}

__device__ __forceinline__ void ldmatrix_x4(uint32_t* r, uint32_t addr) {
    asm volatile("ldmatrix.sync.aligned.m8n8.x4.shared.b16 {%0,%1,%2,%3}, [%4];"
        : "=r"(r[0]), "=r"(r[1]), "=r"(r[2]), "=r"(r[3]) : "r"(addr));
}
// x4 variant loading TWO n8 B-tiles (both k-halves each) in one instruction.
__device__ __forceinline__ void ldmatrix_x4_b(uint32_t* r0, uint32_t* r1,
                                              uint32_t addr) {
    asm volatile("ldmatrix.sync.aligned.m8n8.x4.shared.b16 {%0,%1,%2,%3}, [%4];"
        : "=r"(r0[0]), "=r"(r0[1]), "=r"(r1[0]), "=r"(r1[1]) : "r"(addr));
}
__device__ __forceinline__ void mma_bf16(float* d, const uint32_t* a,
                                         const uint32_t* b) {
    asm volatile(
      "mma.sync.aligned.m16n8k16.row.col.f32.bf16.bf16.f32 "
      "{%0,%1,%2,%3}, {%4,%5,%6,%7}, {%8,%9}, {%0,%1,%2,%3};"
      : "+f"(d[0]), "+f"(d[1]), "+f"(d[2]), "+f"(d[3])
      : "r"(a[0]), "r"(a[1]), "r"(a[2]), "r"(a[3]), "r"(b[0]), "r"(b[1]));
}

// ============================ scratch (no allocs) ==========================
__device__ __nv_bfloat16 g_x_hi[S_LEN * D_MODEL],  g_x_lo[S_LEN * D_MODEL];
__device__ __nv_bfloat16 g_Wq_hi[D_MODEL * D_MODEL], g_Wq_lo[D_MODEL * D_MODEL];
__device__ __nv_bfloat16 g_Wk_hi[D_MODEL * D_MODEL], g_Wk_lo[D_MODEL * D_MODEL];
__device__ __nv_bfloat16 g_Wv_hi[D_MODEL * D_MODEL], g_Wv_lo[D_MODEL * D_MODEL];
__device__ __nv_bfloat16 g_Q_hi[S_LEN * D_MODEL],  g_Q_lo[S_LEN * D_MODEL];
__device__ __nv_bfloat16 g_K_hi[S_LEN * D_MODEL],  g_K_lo[S_LEN * D_MODEL];
__device__ __nv_bfloat16 g_VT_hi[D_MODEL * S_LEN], g_VT_lo[D_MODEL * S_LEN];
__device__ __nv_bfloat16 g_P_hi[(size_t)S_LEN * S_LEN];
__device__ __nv_bfloat16 g_P_lo[(size_t)S_LEN * S_LEN];
__device__ float g_Pscratch[(size_t)S_LEN * S_LEN];  // fallback
__device__ float g_rowsum[S_LEN];

#define ESCALE (1.0f / 32.0f)

// ============================ fused split kernel ===========================
#define N_X  (S_LEN * D_MODEL)
#define N_W  (D_MODEL * D_MODEL)
__global__ void split_all_kernel(const float* __restrict__ x,
                                 const float* __restrict__ Wq,
                                 const float* __restrict__ Wk,
                                 const float* __restrict__ Wv,
                                 __nv_bfloat16* __restrict__ xh,  __nv_bfloat16* __restrict__ xl,
                                 __nv_bfloat16* __restrict__ wqh, __nv_bfloat16* __restrict__ wql,
                                 __nv_bfloat16* __restrict__ wkh, __nv_bfloat16* __restrict__ wkl,
                                 __nv_bfloat16* __restrict__ wvh, __nv_bfloat16* __restrict__ wvl,
                                 float* __restrict__ rowsum)
{
    const int v = blockIdx.x * blockDim.x + threadIdx.x;   // float4 index
    const int NV_X = N_X / 4, NV_W = N_W / 4;
    // first S_LEN threads also zero the rowsum buffer
    if (v < S_LEN) rowsum[v] = 0.f;
    const float* src; __nv_bfloat16* hi; __nv_bfloat16* lo; int idx;
    if (v < NV_X)                 { src = x;  hi = xh;  lo = xl;  idx = v; }
    else if (v < NV_X + NV_W)     { src = Wq; hi = wqh; lo = wql; idx = v - NV_X; }
    else if (v < NV_X + 2 * NV_W) { src = Wk; hi = wkh; lo = wkl; idx = v - NV_X - NV_W; }
    else if (v < NV_X + 3 * NV_W) { src = Wv; hi = wvh; lo = wvl; idx = v - NV_X - 2 * NV_W; }
    else return;

    float4 f = reinterpret_cast<const float4*>(src)[idx];
    __nv_bfloat162 h0, h1, l0, l1;
    h0.x = __float2bfloat16(f.x); l0.x = __float2bfloat16(f.x - __bfloat162float(h0.x));
    h0.y = __float2bfloat16(f.y); l0.y = __float2bfloat16(f.y - __bfloat162float(h0.y));
    h1.x = __float2bfloat16(f.z); l1.x = __float2bfloat16(f.z - __bfloat162float(h1.x));
    h1.y = __float2bfloat16(f.w); l1.y = __float2bfloat16(f.w - __bfloat162float(h1.y));
    reinterpret_cast<__nv_bfloat162*>(hi)[idx * 2 + 0] = h0;
    reinterpret_cast<__nv_bfloat162*>(hi)[idx * 2 + 1] = h1;
    reinterpret_cast<__nv_bfloat162*>(lo)[idx * 2 + 0] = l0;
    reinterpret_cast<__nv_bfloat162*>(lo)[idx * 2 + 1] = l1;
}

// ============================ mma.sync GEMM ================================
// C[M,N] = A[M,K] @ B[N,K]^T, bf16x3 split, fp32 accum.
// 128 threads = 4 warps (2x2), warp tile 64x64.
// XOR-swizzled smem, 3-stage cp.async pipeline, ONE __syncthreads per chunk.
// All fragment loads issued one MMA phase early, INCLUDING the chunk-start
// fragments (prefetched at the tail of the previous chunk after cp_wait).
// Optional epilogue: exp(v/32) + atomic per-row sums (scores GEMM).
#define BM 128
#define BN 128
#define BK 32
#define NTHREADS 128
#define TILE_BYTES (BM * BK * 2)          // 8192
#define STAGE_BYTES (4 * TILE_BYTES)      // 32768 (Ah,Al,Bh,Bl)
#define NSTAGE 3
#define GEMM_SMEM_BYTES (NSTAGE * STAGE_BYTES)  // 98304

// byte offset of 16B granule (r, c16) within a tile
#define SWZ_OFF(r, c16) ((uint32_t)((r) * 64 + (((c16) ^ (((r) >> 1) & 3)) * 16)))

__device__ __forceinline__ void load_tile(
    const __nv_bfloat16* __restrict__ g, int row0, int K, int k0,
    uint32_t sm_base_bytes, int tid)
{
    #pragma unroll
    for (int j = 0; j < 4; j++) {
        int v = tid + j * NTHREADS;     // 0..511 16B granules
        int r = v >> 2;                 // 0..127
        int c16 = v & 3;                // 0..3
        const void* gp = g + (size_t)(row0 + r) * K + k0 + c16 * 8;
        cp_async16(sm_base_bytes + SWZ_OFF(r, c16), gp);
    }
}

__device__ __forceinline__ void gemm_core(
    const __nv_bfloat16* __restrict__ A_hi, const __nv_bfloat16* __restrict__ A_lo,
    const __nv_bfloat16* __restrict__ B_hi, const __nv_bfloat16* __restrict__ B_lo,
    float* __restrict__ Cf,
    __nv_bfloat16* __restrict__ C_hi, __nv_bfloat16* __restrict__ C_lo,
    float* __restrict__ rowsum,
    int M, int N, int K, int m0, int n0)
{
    extern __shared__ __nv_bfloat16 smem[];
    const int tid = threadIdx.x;
    const int wid = tid >> 5;
    const int lane = tid & 31;
    const int wm = wid >> 1;            // 0..1 (64-row band)
    const int wn = wid & 1;             // 0..1 (64-col band)

    const uint32_t sb = smem_u32(smem);
    auto tile_base = [&](int s, int t) -> uint32_t {
        return sb + (uint32_t)(s * STAGE_BYTES + t * TILE_BYTES);
    };
    auto load_chunk = [&](int slot, int k0) {
        load_tile(A_hi, m0, K, k0, tile_base(slot, 0), tid);
        load_tile(A_lo, m0, K, k0, tile_base(slot, 1), tid);
        load_tile(B_hi, n0, K, k0, tile_base(slot, 2), tid);
        load_tile(B_lo, n0, K, k0, tile_base(slot, 3), tid);
    };

    float acc[4][8][4];                 // 128 regs: 4 mt x 8 nt x 4
    #pragma unroll
    for (int a = 0; a < 4; a++)
        #pragma unroll
        for (int b = 0; b < 8; b++)
            #pragma unroll
            for (int c = 0; c < 4; c++) acc[a][b][c] = 0.f;

    const int nch = K / BK;

    // lane-address components
    const int a_r = wm * 64 + (lane & 15);
    const int a_g = lane >> 4;                       // 0..1
    const int b_r = wn * 64 + (lane & 7) + ((lane >> 4) << 3);
    const int b_g = (lane >> 3) & 1;

    uint32_t ah0[4][4], ah1[4][4], bh0[8][2], bh1[8][2];
    uint32_t al[4][4], bl[8][2];

    // prologue: stages 0 and 1 in flight, prefetch chunk0 ks0 fragments
    load_chunk(0, 0);  CP_COMMIT();
    load_chunk(1, BK); CP_COMMIT();
    cp_wait<1>();
    __syncthreads();
    {
        const uint32_t aAh = tile_base(0, 0);
        const uint32_t aAl = tile_base(0, 1);
        const uint32_t aBh = tile_base(0, 2);
        #pragma unroll
        for (int mt = 0; mt < 4; mt++)
            ldmatrix_x4(ah0[mt], aAh + SWZ_OFF(a_r + mt * 16, a_g));
        #pragma unroll
        for (int np = 0; np < 4; np++)
            ldmatrix_x4_b(bh0[np * 2], bh0[np * 2 + 1],
                          aBh + SWZ_OFF(b_r + np * 16, b_g));
        #pragma unroll
        for (int mt = 0; mt < 4; mt++)
            ldmatrix_x4(al[mt], aAl + SWZ_OFF(a_r + mt * 16, a_g));
    }

    for (int i = 0; i < nch; i++) {
        __syncthreads();   // all warps done reading chunk i-1's slot

        if (i + 2 < nch) {
            load_chunk((i + 2) % NSTAGE, (i + 2) * BK);   // slot (i-1)%3
            CP_COMMIT();
        }

        const int s = i % NSTAGE;
        const uint32_t aAh = tile_base(s, 0);
        const uint32_t aAl = tile_base(s, 1);
        const uint32_t aBh = tile_base(s, 2);
        const uint32_t aBl = tile_base(s, 3);

        const int ac1 = 2 + a_g, bc1 = 2 + b_g;      // ks=1 granule cols

        // MMA hh0 (fragments prefetched at previous chunk's tail / prologue)
        #pragma unroll
        for (int mt = 0; mt < 4; mt++)
            #pragma unroll
            for (int nt = 0; nt < 8; nt++)
                mma_bf16(acc[mt][nt], ah0[mt], bh0[nt]);

        // L: bl (ks0) — completes under hh0 drain
        #pragma unroll
        for (int np = 0; np < 4; np++)
            ldmatrix_x4_b(bl[np * 2], bl[np * 2 + 1],
                          aBl + SWZ_OFF(b_r + np * 16, b_g));

        // MMA lh0 (al x bh0)
        #pragma unroll
        for (int mt = 0; mt < 4; mt++)
            #pragma unroll
            for (int nt = 0; nt < 8; nt++)
                mma_bf16(acc[mt][nt], al[mt], bh0[nt]);

        // L: ah1, bh1 — complete under hl0
        #pragma unroll
        for (int mt = 0; mt < 4; mt++)
            ldmatrix_x4(ah1[mt], aAh + SWZ_OFF(a_r + mt * 16, ac1));
        #pragma unroll
        for (int np = 0; np < 4; np++)
            ldmatrix_x4_b(bh1[np * 2], bh1[np * 2 + 1],
                          aBh + SWZ_OFF(b_r + np * 16, bc1));

        // MMA hl0 (ah0 x bl)
        #pragma unroll
        for (int mt = 0; mt < 4; mt++)
            #pragma unroll
            for (int nt = 0; nt < 8; nt++)
                mma_bf16(acc[mt][nt], ah0[mt], bl[nt]);

        // L: al (ks1) — completes under hh1
        #pragma unroll
        for (int mt = 0; mt < 4; mt++)
            ldmatrix_x4(al[mt], aAl + SWZ_OFF(a_r + mt * 16, ac1));

        // MMA hh1
        #pragma unroll
        for (int mt = 0; mt < 4; mt++)
            #pragma unroll
            for (int nt = 0; nt < 8; nt++)
                mma_bf16(acc[mt][nt], ah1[mt], bh1[nt]);

        // L: bl (ks1) — completes under lh1
        #pragma unroll
        for (int np = 0; np < 4; np++)
            ldmatrix_x4_b(bl[np * 2], bl[np * 2 + 1],
                          aBl + SWZ_OFF(b_r + np * 16, bc1));

        // MMA lh1
        #pragma unroll
        for (int mt = 0; mt < 4; mt++)
            #pragma unroll
            for (int nt = 0; nt < 8; nt++)
                mma_bf16(acc[mt][nt], al[mt], bh1[nt]);

        // MMA hl1
        #pragma unroll
        for (int mt = 0; mt < 4; mt++)
            #pragma unroll
            for (int nt = 0; nt < 8; nt++)
                mma_bf16(acc[mt][nt], ah1[mt], bl[nt]);

        // tail: prefetch chunk i+1's ks0 fragments (covers the post-barrier load)
        if (i + 1 < nch) {
            if (i + 2 < nch) cp_wait<1>(); else cp_wait<0>();
            const int s2 = (i + 1) % NSTAGE;
            const uint32_t nAh = tile_base(s2, 0);
            const uint32_t nAl = tile_base(s2, 1);
            const uint32_t nBh = tile_base(s2, 2);
            #pragma unroll
            for (int mt = 0; mt < 4; mt++)
                ldmatrix_x4(ah0[mt], nAh + SWZ_OFF(a_r + mt * 16, a_g));
            #pragma unroll
            for (int np = 0; np < 4; np++)
                ldmatrix_x4_b(bh0[np * 2], bh0[np * 2 + 1],
                              nBh + SWZ_OFF(b_r + np * 16, b_g));
            #pragma unroll
            for (int mt = 0; mt < 4; mt++)
                ldmatrix_x4(al[mt], nAl + SWZ_OFF(a_r + mt * 16, a_g));
        }
    }

    // epilogue
    const int tr = lane >> 2;           // 0..7
    const int tc = (lane & 3) * 2;      // 0,2,4,6
    const int r0 = m0 + wm * 64;
    const int c0 = n0 + wn * 64;

    #pragma unroll
    for (int mt = 0; mt < 4; mt++) {
        float rs0 = 0.f, rs1 = 0.f;
        #pragma unroll
        for (int nt = 0; nt < 8; nt++) {
            const float* d = acc[mt][nt];
            const int row = r0 + mt * 16 + tr;
            const int col = c0 + nt * 8 + tc;
            if (Cf != nullptr) {
                float d0 = d[0], d1 = d[1], d2 = d[2], d3 = d[3];
                if (rowsum != nullptr) {
                    d0 = __expf(d0 * ESCALE); d1 = __expf(d1 * ESCALE);
                    d2 = __expf(d2 * ESCALE); d3 = __expf(d3 * ESCALE);
                    rs0 += d0 + d1; rs1 += d2 + d3;
                }
                *reinterpret_cast<float2*>(&Cf[(size_t)row * N + col]) =
                    make_float2(d0, d1);
                *reinterpret_cast<float2*>(&Cf[(size_t)(row + 8) * N + col]) =
                    make_float2(d2, d3);
            } else {
                #pragma unroll
                for (int e = 0; e < 2; e++) {
                    const int rr = row + e * 8;
                    __nv_bfloat162 h2, l2;
                    {
                        float v = d[e * 2 + 0];
                        __nv_bfloat16 h = __float2bfloat16(v);
                        h2.x = h; l2.x = __float2bfloat16(v - __bfloat162float(h));
                    }
                    {
                        float v = d[e * 2 + 1];
                        __nv_bfloat16 h = __float2bfloat16(v);
                        h2.y = h; l2.y = __float2bfloat16(v - __bfloat162float(h));
                    }
                    *reinterpret_cast<__nv_bfloat162*>(
                        &C_hi[(size_t)rr * N + col]) = h2;
                    *reinterpret_cast<__nv_bfloat162*>(
                        &C_lo[(size_t)rr * N + col]) = l2;
                }
            }
        }
        if (Cf != nullptr && rowsum != nullptr) {
            // quad reduce (lanes sharing tr): tc varies over lane&3
            rs0 += __shfl_xor_sync(0xffffffffu, rs0, 1);
            rs0 += __shfl_xor_sync(0xffffffffu, rs0, 2);
            rs1 += __shfl_xor_sync(0xffffffffu, rs1, 1);
            rs1 += __shfl_xor_sync(0xffffffffu, rs1, 2);
            if ((lane & 3) == 0) {
                atomicAdd(&rowsum[r0 + mt * 16 + tr], rs0);
                atomicAdd(&rowsum[r0 + mt * 16 + tr + 8], rs1);
            }
        }
    }
}

// ============================ GEMM kernels =================================
__global__ void __launch_bounds__(NTHREADS)
gemm_main(const __nv_bfloat16* __restrict__ A_hi, const __nv_bfloat16* __restrict__ A_lo,
          const __nv_bfloat16* __restrict__ B_hi, const __nv_bfloat16* __restrict__ B_lo,
          float* __restrict__ Cf,
          __nv_bfloat16* __restrict__ C_hi, __nv_bfloat16* __restrict__ C_lo,
          float* __restrict__ rowsum,
          int M, int N, int K)
{
    gemm_core(A_hi, A_lo, B_hi, B_lo, Cf, C_hi, C_lo, rowsum, M, N, K,
              blockIdx.y * BM, blockIdx.x * BN);
}

struct ProjSet {
    const __nv_bfloat16 *Ah, *Al, *Bh, *Bl;
    __nv_bfloat16 *Ch, *Cl;
    int M, N, K, gx;
};

// All three projection GEMMs in one 768-CTA launch (256 CTAs each).
__global__ void __launch_bounds__(NTHREADS)
proj_fused_kernel(ProjSet s0, ProjSet s1, ProjSet s2)
{
    const int b = blockIdx.x;
    ProjSet s = (b < 256) ? s0 : (b < 512) ? s1 : s2;
    const int r = b & 255;
    const int bx = r % s.gx;
    const int by = r / s.gx;
    gemm_core(s.Ah, s.Al, s.Bh, s.Bl, nullptr, s.Ch, s.Cl, nullptr,
              s.M, s.N, s.K, by * BM, bx * BN);
}

// ============================ normalize (1 pass) ===========================
// P already holds exp(score/32) (written by the scores GEMM epilogue) and
// rowsum[r] the row sums. Normalize and emit fp32 + bf16 hi/lo.
__global__ void normalize_rows_kernel(float* __restrict__ P,
                                      const float* __restrict__ rowsum,
                                      __nv_bfloat16* __restrict__ Phi,
                                      __nv_bfloat16* __restrict__ Plo, int n)
{
    float4* p4 = reinterpret_cast<float4*>(P + (size_t)blockIdx.x * n);
    __nv_bfloat162* ph2 = reinterpret_cast<__nv_bfloat162*>(Phi + (size_t)blockIdx.x * n);
    __nv_bfloat162* pl2 = reinterpret_cast<__nv_bfloat162*>(Plo + (size_t)blockIdx.x * n);
    const int t = threadIdx.x;
    const int nv = n / 4;
    const float inv = 1.f / rowsum[blockIdx.x];

    for (int i = t; i < nv; i += 256) {
        float4 f = p4[i];
        f.x *= inv; f.y *= inv; f.z *= inv; f.w *= inv;
        p4[i] = f;
        __nv_bfloat162 h0, h1, l0, l1;
        h0.x = __float2bfloat16(f.x); l0.x = __float2bfloat16(f.x - __bfloat162float(h0.x));
        h0.y = __float2bfloat16(f.y); l0.y = __float2bfloat16(f.y - __bfloat162float(h0.y));
        h1.x = __float2bfloat16(f.z); l1.x = __float2bfloat16(f.z - __bfloat162float(h1.x));
        h1.y = __float2bfloat16(f.w); l1.y = __float2bfloat16(f.w - __bfloat162float(h1.y));
        ph2[i * 2 + 0] = h0; ph2[i * 2 + 1] = h1;
        pl2[i * 2 + 0] = l0; pl2[i * 2 + 1] = l1;
    }
}

// ============================ launch =======================================
extern "C" void kernel_launch(void* const* d_in, const int* in_sizes, int n_in,
                              void* d_out, int out_size)
{
    const float* x  = (const float*)d_in[0];
    const float* Wq = (const float*)d_in[1];
    const float* Wk = (const float*)d_in[2];
    const float* Wv = (const float*)d_in[3];
    float* out = (float*)d_out;

    __nv_bfloat16 *xh, *xl, *wqh, *wql, *wkh, *wkl, *wvh, *wvl;
    __nv_bfloat16 *qh, *ql, *kh, *kl, *vth, *vtl, *pph, *ppl;
    float *dPs, *drs;
    cudaGetSymbolAddress((void**)&xh,  g_x_hi);  cudaGetSymbolAddress((void**)&xl,  g_x_lo);
    cudaGetSymbolAddress((void**)&wqh, g_Wq_hi); cudaGetSymbolAddress((void**)&wql, g_Wq_lo);
    cudaGetSymbolAddress((void**)&wkh, g_Wk_hi); cudaGetSymbolAddress((void**)&wkl, g_Wk_lo);
    cudaGetSymbolAddress((void**)&wvh, g_Wv_hi); cudaGetSymbolAddress((void**)&wvl, g_Wv_lo);
    cudaGetSymbolAddress((void**)&qh,  g_Q_hi);  cudaGetSymbolAddress((void**)&ql,  g_Q_lo);
    cudaGetSymbolAddress((void**)&kh,  g_K_hi);  cudaGetSymbolAddress((void**)&kl,  g_K_lo);
    cudaGetSymbolAddress((void**)&vth, g_VT_hi); cudaGetSymbolAddress((void**)&vtl, g_VT_lo);
    cudaGetSymbolAddress((void**)&pph, g_P_hi);  cudaGetSymbolAddress((void**)&ppl, g_P_lo);
    cudaGetSymbolAddress((void**)&dPs, g_Pscratch);
    cudaGetSymbolAddress((void**)&drs, g_rowsum);

    float* Vs = out;
    const long long need = (long long)S_LEN * D_MODEL + (long long)S_LEN * S_LEN;
    float* P = (out_size >= need) ? (out + (size_t)S_LEN * D_MODEL) : dPs;

    cudaFuncSetAttribute(gemm_main,
                         cudaFuncAttributeMaxDynamicSharedMemorySize,
                         GEMM_SMEM_BYTES);
    cudaFuncSetAttribute(proj_fused_kernel,
                         cudaFuncAttributeMaxDynamicSharedMemorySize,
                         GEMM_SMEM_BYTES);

    // fused split: x + Wq + Wk + Wv (also zeros rowsum)
    {
        int total_vec = (N_X + 3 * N_W) / 4;
        split_all_kernel<<<(total_vec + 255) / 256, 256>>>(
            x, Wq, Wk, Wv, xh, xl, wqh, wql, wkh, wkl, wvh, wvl, drs);
    }

    dim3 blk(NTHREADS);

    // Q = x@Wq^T [S,D] ; K = x@Wk^T [S,D] ; V^T = Wv@x^T [D,S]  (one launch)
    ProjSet sq{xh, xl, wqh, wql, qh, ql, S_LEN, D_MODEL, D_MODEL, D_MODEL / BN};
    ProjSet sk{xh, xl, wkh, wkl, kh, kl, S_LEN, D_MODEL, D_MODEL, D_MODEL / BN};
    ProjSet sv{wvh, wvl, xh, xl, vth, vtl, D_MODEL, S_LEN, D_MODEL, S_LEN / BN};
    proj_fused_kernel<<<768, blk, GEMM_SMEM_BYTES>>>(sq, sk, sv);

    // exp(scores/32) = exp(Q.K^T/32) -> P, + atomic row sums
    gemm_main<<<dim3(S_LEN / BN, S_LEN / BM), blk, GEMM_SMEM_BYTES>>>(
        qh, ql, kh, kl, P, nullptr, nullptr, drs, S_LEN, S_LEN, D_MODEL);

    // normalize rows, emit fp32 P + bf16 hi/lo
    normalize_rows_kernel<<<S_LEN, 256>>>(P, drs, pph, ppl, S_LEN);

    // Vs = P @ (V^T)^T -> fp32  [S, D]
    gemm_main<<<dim3(D_MODEL / BN, S_LEN / BM), blk, GEMM_SMEM_BYTES>>>(
        pph, ppl, vth, vtl, Vs, nullptr, nullptr, nullptr, S_LEN, D_MODEL, S_LEN);
}

// round 13
// speedup vs baseline: 1.0119x; 1.0119x over previous
#include <cuda_runtime.h>
#include <cuda_bf16.h>
#include <math.h>
#include <cstdint>

#define S_LEN 4096
#define D_MODEL 1024

// ============================ PTX helpers (sm_80-class only) ===============
__device__ __forceinline__ uint32_t smem_u32(const void* p) {
    uint32_t a;
    asm("{ .reg .u64 t; cvta.to.shared.u64 t, %1; cvt.u32.u64 %0, t; }"
        : "=r"(a) : "l"(p));
    return a;
}

__device__ __forceinline__ void cp_async16(uint32_t smem_addr, const void* gptr) {
    asm volatile("cp.async.cg.shared.global [%0], [%1], 16;"
                 :: "r"(smem_addr), "l"(gptr));
}
#define CP_COMMIT() asm volatile("cp.async.commit_group;" ::: "memory")
template<int N> __device__ __forceinline__ void cp_wait() {
    asm volatile("cp.async.wait_group %0;" :: "n"(N) : "memory");
}

__device__ __forceinline__ void ldmatrix_x4(uint32_t* r, uint32_t addr) {
    asm volatile("ldmatrix.sync.aligned.m8n8.x4.shared.b16 {%0,%1,%2,%3}, [%4];"
        : "=r"(r[0]), "=r"(r[1]), "=r"(r[2]), "=r"(r[3]) : "r"(addr));
}
// x4 variant loading TWO n8 B-tiles (both k-halves each) in one instruction.
__device__ __forceinline__ void ldmatrix_x4_b(uint32_t* r0, uint32_t* r1,
                                              uint32_t addr) {
    asm volatile("ldmatrix.sync.aligned.m8n8.x4.shared.b16 {%0,%1,%2,%3}, [%4];"
        : "=r"(r0[0]), "=r"(r0[1]), "=r"(r1[0]), "=r"(r1[1]) : "r"(addr));
}
__device__ __forceinline__ void mma_bf16(float* d, const uint32_t* a,
                                         const uint32_t* b) {
    asm volatile(
      "mma.sync.aligned.m16n8k16.row.col.f32.bf16.bf16.f32 "
      "{%0,%1,%2,%3}, {%4,%5,%6,%7}, {%8,%9}, {%0,%1,%2,%3};"
      : "+f"(d[0]), "+f"(d[1]), "+f"(d[2]), "+f"(d[3])
      : "r"(a[0]), "r"(a[1]), "r"(a[2]), "r"(a[3]), "r"(b[0]), "r"(b[1]));
}

// ============================ scratch (no allocs) ==========================
__device__ __nv_bfloat16 g_x_hi[S_LEN * D_MODEL],  g_x_lo[S_LEN * D_MODEL];
__device__ __nv_bfloat16 g_Wq_hi[D_MODEL * D_MODEL], g_Wq_lo[D_MODEL * D_MODEL];
__device__ __nv_bfloat16 g_Wk_hi[D_MODEL * D_MODEL], g_Wk_lo[D_MODEL * D_MODEL];
__device__ __nv_bfloat16 g_Wv_hi[D_MODEL * D_MODEL], g_Wv_lo[D_MODEL * D_MODEL];
__device__ __nv_bfloat16 g_Q_hi[S_LEN * D_MODEL],  g_Q_lo[S_LEN * D_MODEL];
__device__ __nv_bfloat16 g_K_hi[S_LEN * D_MODEL],  g_K_lo[S_LEN * D_MODEL];
__device__ __nv_bfloat16 g_VT_hi[D_MODEL * S_LEN], g_VT_lo[D_MODEL * S_LEN];
__device__ __nv_bfloat16 g_P_hi[(size_t)S_LEN * S_LEN];
__device__ __nv_bfloat16 g_P_lo[(size_t)S_LEN * S_LEN];
__device__ float g_Pscratch[(size_t)S_LEN * S_LEN];  // fallback

// ============================ fused split kernel ===========================
#define N_X  (S_LEN * D_MODEL)
#define N_W  (D_MODEL * D_MODEL)
__global__ void split_all_kernel(const float* __restrict__ x,
                                 const float* __restrict__ Wq,
                                 const float* __restrict__ Wk,
                                 const float* __restrict__ Wv,
                                 __nv_bfloat16* __restrict__ xh,  __nv_bfloat16* __restrict__ xl,
                                 __nv_bfloat16* __restrict__ wqh, __nv_bfloat16* __restrict__ wql,
                                 __nv_bfloat16* __restrict__ wkh, __nv_bfloat16* __restrict__ wkl,
                                 __nv_bfloat16* __restrict__ wvh, __nv_bfloat16* __restrict__ wvl)
{
    const int v = blockIdx.x * blockDim.x + threadIdx.x;   // float4 index
    const int NV_X = N_X / 4, NV_W = N_W / 4;
    const float* src; __nv_bfloat16* hi; __nv_bfloat16* lo; int idx;
    if (v < NV_X)                 { src = x;  hi = xh;  lo = xl;  idx = v; }
    else if (v < NV_X + NV_W)     { src = Wq; hi = wqh; lo = wql; idx = v - NV_X; }
    else if (v < NV_X + 2 * NV_W) { src = Wk; hi = wkh; lo = wkl; idx = v - NV_X - NV_W; }
    else if (v < NV_X + 3 * NV_W) { src = Wv; hi = wvh; lo = wvl; idx = v - NV_X - 2 * NV_W; }
    else return;

    float4 f = reinterpret_cast<const float4*>(src)[idx];
    __nv_bfloat162 h0, h1, l0, l1;
    h0.x = __float2bfloat16(f.x); l0.x = __float2bfloat16(f.x - __bfloat162float(h0.x));
    h0.y = __float2bfloat16(f.y); l0.y = __float2bfloat16(f.y - __bfloat162float(h0.y));
    h1.x = __float2bfloat16(f.z); l1.x = __float2bfloat16(f.z - __bfloat162float(h1.x));
    h1.y = __float2bfloat16(f.w); l1.y = __float2bfloat16(f.w - __bfloat162float(h1.y));
    reinterpret_cast<__nv_bfloat162*>(hi)[idx * 2 + 0] = h0;
    reinterpret_cast<__nv_bfloat162*>(hi)[idx * 2 + 1] = h1;
    reinterpret_cast<__nv_bfloat162*>(lo)[idx * 2 + 0] = l0;
    reinterpret_cast<__nv_bfloat162*>(lo)[idx * 2 + 1] = l1;
}

// ============================ mma.sync GEMM ================================
// C[M,N] = A[M,K] @ B[N,K]^T, bf16x3 split, fp32 accum.
// 128 threads = 4 warps (2x2), warp tile 64x64.
// XOR-swizzled smem, 3-stage cp.async pipeline, ONE __syncthreads per chunk.
// Fragment loads issued ONE MMA PHASE EARLY so each ldmatrix burst completes
// under the previous 32-MMA phase (issue + drain >> smem latency).
#define BM 128
#define BN 128
#define BK 32
#define NTHREADS 128
#define TILE_BYTES (BM * BK * 2)          // 8192
#define STAGE_BYTES (4 * TILE_BYTES)      // 32768 (Ah,Al,Bh,Bl)
#define NSTAGE 3
#define GEMM_SMEM_BYTES (NSTAGE * STAGE_BYTES)  // 98304

// byte offset of 16B granule (r, c16) within a tile
#define SWZ_OFF(r, c16) ((uint32_t)((r) * 64 + (((c16) ^ (((r) >> 1) & 3)) * 16)))

__device__ __forceinline__ void load_tile(
    const __nv_bfloat16* __restrict__ g, int row0, int K, int k0,
    uint32_t sm_base_bytes, int tid)
{
    #pragma unroll
    for (int j = 0; j < 4; j++) {
        int v = tid + j * NTHREADS;     // 0..511 16B granules
        int r = v >> 2;                 // 0..127
        int c16 = v & 3;                // 0..3
        const void* gp = g + (size_t)(row0 + r) * K + k0 + c16 * 8;
        cp_async16(sm_base_bytes + SWZ_OFF(r, c16), gp);
    }
}

__device__ __forceinline__ void gemm_core(
    const __nv_bfloat16* __restrict__ A_hi, const __nv_bfloat16* __restrict__ A_lo,
    const __nv_bfloat16* __restrict__ B_hi, const __nv_bfloat16* __restrict__ B_lo,
    float* __restrict__ Cf,
    __nv_bfloat16* __restrict__ C_hi, __nv_bfloat16* __restrict__ C_lo,
    int M, int N, int K, int m0, int n0)
{
    extern __shared__ __nv_bfloat16 smem[];
    const int tid = threadIdx.x;
    const int wid = tid >> 5;
    const int lane = tid & 31;
    const int wm = wid >> 1;            // 0..1 (64-row band)
    const int wn = wid & 1;             // 0..1 (64-col band)

    const uint32_t sb = smem_u32(smem);
    auto tile_base = [&](int s, int t) -> uint32_t {
        return sb + (uint32_t)(s * STAGE_BYTES + t * TILE_BYTES);
    };
    auto load_chunk = [&](int slot, int k0) {
        load_tile(A_hi, m0, K, k0, tile_base(slot, 0), tid);
        load_tile(A_lo, m0, K, k0, tile_base(slot, 1), tid);
        load_tile(B_hi, n0, K, k0, tile_base(slot, 2), tid);
        load_tile(B_lo, n0, K, k0, tile_base(slot, 3), tid);
    };

    float acc[4][8][4];                 // 128 regs: 4 mt x 8 nt x 4
    #pragma unroll
    for (int a = 0; a < 4; a++)
        #pragma unroll
        for (int b = 0; b < 8; b++)
            #pragma unroll
            for (int c = 0; c < 4; c++) acc[a][b][c] = 0.f;

    const int nch = K / BK;

    // prologue: stages 0 and 1 in flight
    load_chunk(0, 0);  CP_COMMIT();
    load_chunk(1, BK); CP_COMMIT();

    // lane-address components
    const int a_r = wm * 64 + (lane & 15);
    const int a_g = lane >> 4;                       // 0..1
    const int b_r = wn * 64 + (lane & 7) + ((lane >> 4) << 3);
    const int b_g = (lane >> 3) & 1;

    for (int i = 0; i < nch; i++) {
        if (i == nch - 1) cp_wait<0>(); else cp_wait<1>();
        __syncthreads();   // also guarantees stage (i+2)%3 fully consumed

        if (i + 2 < nch) {
            load_chunk((i + 2) % NSTAGE, (i + 2) * BK);
            CP_COMMIT();
        }

        const int s = i % NSTAGE;
        const uint32_t aAh = tile_base(s, 0);
        const uint32_t aAl = tile_base(s, 1);
        const uint32_t aBh = tile_base(s, 2);
        const uint32_t aBl = tile_base(s, 3);

        const int ac0 = a_g,     bc0 = b_g;          // ks=0 granule cols
        const int ac1 = 2 + a_g, bc1 = 2 + b_g;      // ks=1 granule cols

        uint32_t ah0[4][4], ah1[4][4], bh0[8][2], bh1[8][2];
        uint32_t al[4][4], bl[8][2];

        // --- loads staged one MMA phase ahead of their consumers ---

        // L: ah0, bh0 (exposed: chunk start, right after barrier)
        #pragma unroll
        for (int mt = 0; mt < 4; mt++)
            ldmatrix_x4(ah0[mt], aAh + SWZ_OFF(a_r + mt * 16, ac0));
        #pragma unroll
        for (int np = 0; np < 4; np++)
            ldmatrix_x4_b(bh0[np * 2], bh0[np * 2 + 1],
                          aBh + SWZ_OFF(b_r + np * 16, bc0));
        // L: al (ks0) — completes under hh0
        #pragma unroll
        for (int mt = 0; mt < 4; mt++)
            ldmatrix_x4(al[mt], aAl + SWZ_OFF(a_r + mt * 16, ac0));

        // MMA hh0
        #pragma unroll
        for (int mt = 0; mt < 4; mt++)
            #pragma unroll
            for (int nt = 0; nt < 8; nt++)
                mma_bf16(acc[mt][nt], ah0[mt], bh0[nt]);

        // L: bl (ks0) — completes under lh0
        #pragma unroll
        for (int np = 0; np < 4; np++)
            ldmatrix_x4_b(bl[np * 2], bl[np * 2 + 1],
                          aBl + SWZ_OFF(b_r + np * 16, bc0));

        // MMA lh0 (al x bh0; both die after)
        #pragma unroll
        for (int mt = 0; mt < 4; mt++)
            #pragma unroll
            for (int nt = 0; nt < 8; nt++)
                mma_bf16(acc[mt][nt], al[mt], bh0[nt]);

        // L: ah1, bh1 — complete under hl0
        #pragma unroll
        for (int mt = 0; mt < 4; mt++)
            ldmatrix_x4(ah1[mt], aAh + SWZ_OFF(a_r + mt * 16, ac1));
        #pragma unroll
        for (int np = 0; np < 4; np++)
            ldmatrix_x4_b(bh1[np * 2], bh1[np * 2 + 1],
                          aBh + SWZ_OFF(b_r + np * 16, bc1));

        // MMA hl0 (ah0 x bl; both die after)
        #pragma unroll
        for (int mt = 0; mt < 4; mt++)
            #pragma unroll
            for (int nt = 0; nt < 8; nt++)
                mma_bf16(acc[mt][nt], ah0[mt], bl[nt]);

        // L: al (ks1) — completes under hh1
        #pragma unroll
        for (int mt = 0; mt < 4; mt++)
            ldmatrix_x4(al[mt], aAl + SWZ_OFF(a_r + mt * 16, ac1));

        // MMA hh1
        #pragma unroll
        for (int mt = 0; mt < 4; mt++)
            #pragma unroll
            for (int nt = 0; nt < 8; nt++)
                mma_bf16(acc[mt][nt], ah1[mt], bh1[nt]);

        // L: bl (ks1) — completes under lh1
        #pragma unroll
        for (int np = 0; np < 4; np++)
            ldmatrix_x4_b(bl[np * 2], bl[np * 2 + 1],
                          aBl + SWZ_OFF(b_r + np * 16, bc1));

        // MMA lh1
        #pragma unroll
        for (int mt = 0; mt < 4; mt++)
            #pragma unroll
            for (int nt = 0; nt < 8; nt++)
                mma_bf16(acc[mt][nt], al[mt], bh1[nt]);

        // MMA hl1
        #pragma unroll
        for (int mt = 0; mt < 4; mt++)
            #pragma unroll
            for (int nt = 0; nt < 8; nt++)
                mma_bf16(acc[mt][nt], ah1[mt], bl[nt]);
    }

    // epilogue
    const int tr = lane >> 2;           // 0..7
    const int tc = (lane & 3) * 2;      // 0,2,4,6
    const int r0 = m0 + wm * 64;
    const int c0 = n0 + wn * 64;

    #pragma unroll
    for (int mt = 0; mt < 4; mt++) {
        #pragma unroll
        for (int nt = 0; nt < 8; nt++) {
            const float* d = acc[mt][nt];
            const int row = r0 + mt * 16 + tr;
            const int col = c0 + nt * 8 + tc;
            if (Cf != nullptr) {
                *reinterpret_cast<float2*>(&Cf[(size_t)row * N + col]) =
                    make_float2(d[0], d[1]);
                *reinterpret_cast<float2*>(&Cf[(size_t)(row + 8) * N + col]) =
                    make_float2(d[2], d[3]);
            } else {
                #pragma unroll
                for (int e = 0; e < 2; e++) {
                    const int rr = row + e * 8;
                    __nv_bfloat162 h2, l2;
                    {
                        float v = d[e * 2 + 0];
                        __nv_bfloat16 h = __float2bfloat16(v);
                        h2.x = h; l2.x = __float2bfloat16(v - __bfloat162float(h));
                    }
                    {
                        float v = d[e * 2 + 1];
                        __nv_bfloat16 h = __float2bfloat16(v);
                        h2.y = h; l2.y = __float2bfloat16(v - __bfloat162float(h));
                    }
                    *reinterpret_cast<__nv_bfloat162*>(
                        &C_hi[(size_t)rr * N + col]) = h2;
                    *reinterpret_cast<__nv_bfloat162*>(
                        &C_lo[(size_t)rr * N + col]) = l2;
                }
            }
        }
    }
}

// ============================ GEMM kernels =================================
__global__ void __launch_bounds__(NTHREADS)
gemm_main(const __nv_bfloat16* __restrict__ A_hi, const __nv_bfloat16* __restrict__ A_lo,
          const __nv_bfloat16* __restrict__ B_hi, const __nv_bfloat16* __restrict__ B_lo,
          float* __restrict__ Cf,
          __nv_bfloat16* __restrict__ C_hi, __nv_bfloat16* __restrict__ C_lo,
          int M, int N, int K)
{
    gemm_core(A_hi, A_lo, B_hi, B_lo, Cf, C_hi, C_lo, M, N, K,
              blockIdx.y * BM, blockIdx.x * BN);
}

struct ProjSet {
    const __nv_bfloat16 *Ah, *Al, *Bh, *Bl;
    __nv_bfloat16 *Ch, *Cl;
    int M, N, K, gx;
};

// All three projection GEMMs in one 768-CTA launch (256 CTAs each).
__global__ void __launch_bounds__(NTHREADS)
proj_fused_kernel(ProjSet s0, ProjSet s1, ProjSet s2)
{
    const int b = blockIdx.x;
    ProjSet s = (b < 256) ? s0 : (b < 512) ? s1 : s2;
    const int r = b & 255;
    const int bx = r % s.gx;
    const int by = r / s.gx;
    gemm_core(s.Ah, s.Al, s.Bh, s.Bl, nullptr, s.Ch, s.Cl,
              s.M, s.N, s.K, by * BM, bx * BN);
}

// ============================ softmax (single pass, row in registers) ======
// One block per row; 256 threads x 16 floats = 4096 elems held in registers.
// exp (shift-free: scores/32 are small), block-reduce sum, normalize, emit
// fp32 P + bf16 hi/lo — one read and one write of each output stream.
__global__ void __launch_bounds__(256)
softmax_rows_kernel(float* __restrict__ P,
                    __nv_bfloat16* __restrict__ Phi,
                    __nv_bfloat16* __restrict__ Plo, int n)
{
    float4* p4 = reinterpret_cast<float4*>(P + (size_t)blockIdx.x * n);
    __nv_bfloat162* ph2 = reinterpret_cast<__nv_bfloat162*>(Phi + (size_t)blockIdx.x * n);
    __nv_bfloat162* pl2 = reinterpret_cast<__nv_bfloat162*>(Plo + (size_t)blockIdx.x * n);
    __shared__ float red[256];
    const int t = threadIdx.x;
    const float scale = 1.0f / 32.0f;

    // 4096 / 4 = 1024 float4s; 4 per thread
    float4 v[4];
    float sum = 0.f;
    #pragma unroll
    for (int j = 0; j < 4; j++) {
        float4 f = p4[t + j * 256];
        f.x = __expf(f.x * scale);
        f.y = __expf(f.y * scale);
        f.z = __expf(f.z * scale);
        f.w = __expf(f.w * scale);
        v[j] = f;
        sum += (f.x + f.y) + (f.z + f.w);
    }

    red[t] = sum;
    __syncthreads();
    for (int s = 128; s > 0; s >>= 1) {
        if (t < s) red[t] += red[t + s];
        __syncthreads();
    }
    const float inv = 1.f / red[0];

    #pragma unroll
    for (int j = 0; j < 4; j++) {
        float4 f = v[j];
        f.x *= inv; f.y *= inv; f.z *= inv; f.w *= inv;
        p4[t + j * 256] = f;
        __nv_bfloat162 h0, h1, l0, l1;
        h0.x = __float2bfloat16(f.x); l0.x = __float2bfloat16(f.x - __bfloat162float(h0.x));
        h0.y = __float2bfloat16(f.y); l0.y = __float2bfloat16(f.y - __bfloat162float(h0.y));
        h1.x = __float2bfloat16(f.z); l1.x = __float2bfloat16(f.z - __bfloat162float(h1.x));
        h1.y = __float2bfloat16(f.w); l1.y = __float2bfloat16(f.w - __bfloat162float(h1.y));
        const int i = t + j * 256;
        ph2[i * 2 + 0] = h0; ph2[i * 2 + 1] = h1;
        pl2[i * 2 + 0] = l0; pl2[i * 2 + 1] = l1;
    }
}

// ============================ launch =======================================
extern "C" void kernel_launch(void* const* d_in, const int* in_sizes, int n_in,
                              void* d_out, int out_size)
{
    const float* x  = (const float*)d_in[0];
    const float* Wq = (const float*)d_in[1];
    const float* Wk = (const float*)d_in[2];
    const float* Wv = (const float*)d_in[3];
    float* out = (float*)d_out;

    __nv_bfloat16 *xh, *xl, *wqh, *wql, *wkh, *wkl, *wvh, *wvl;
    __nv_bfloat16 *qh, *ql, *kh, *kl, *vth, *vtl, *pph, *ppl;
    float* dPs;
    cudaGetSymbolAddress((void**)&xh,  g_x_hi);  cudaGetSymbolAddress((void**)&xl,  g_x_lo);
    cudaGetSymbolAddress((void**)&wqh, g_Wq_hi); cudaGetSymbolAddress((void**)&wql, g_Wq_lo);
    cudaGetSymbolAddress((void**)&wkh, g_Wk_hi); cudaGetSymbolAddress((void**)&wkl, g_Wk_lo);
    cudaGetSymbolAddress((void**)&wvh, g_Wv_hi); cudaGetSymbolAddress((void**)&wvl, g_Wv_lo);
    cudaGetSymbolAddress((void**)&qh,  g_Q_hi);  cudaGetSymbolAddress((void**)&ql,  g_Q_lo);
    cudaGetSymbolAddress((void**)&kh,  g_K_hi);  cudaGetSymbolAddress((void**)&kl,  g_K_lo);
    cudaGetSymbolAddress((void**)&vth, g_VT_hi); cudaGetSymbolAddress((void**)&vtl, g_VT_lo);
    cudaGetSymbolAddress((void**)&pph, g_P_hi);  cudaGetSymbolAddress((void**)&ppl, g_P_lo);
    cudaGetSymbolAddress((void**)&dPs, g_Pscratch);

    float* Vs = out;
    const long long need = (long long)S_LEN * D_MODEL + (long long)S_LEN * S_LEN;
    float* P = (out_size >= need) ? (out + (size_t)S_LEN * D_MODEL) : dPs;

    cudaFuncSetAttribute(gemm_main,
                         cudaFuncAttributeMaxDynamicSharedMemorySize,
                         GEMM_SMEM_BYTES);
    cudaFuncSetAttribute(proj_fused_kernel,
                         cudaFuncAttributeMaxDynamicSharedMemorySize,
                         GEMM_SMEM_BYTES);

    // fused split: x + Wq + Wk + Wv, float4-vectorized
    {
        int total_vec = (N_X + 3 * N_W) / 4;
        split_all_kernel<<<(total_vec + 255) / 256, 256>>>(
            x, Wq, Wk, Wv, xh, xl, wqh, wql, wkh, wkl, wvh, wvl);
    }

    dim3 blk(NTHREADS);

    // Q = x@Wq^T [S,D] ; K = x@Wk^T [S,D] ; V^T = Wv@x^T [D,S]  (one launch)
    ProjSet sq{xh, xl, wqh, wql, qh, ql, S_LEN, D_MODEL, D_MODEL, D_MODEL / BN};
    ProjSet sk{xh, xl, wkh, wkl, kh, kl, S_LEN, D_MODEL, D_MODEL, D_MODEL / BN};
    ProjSet sv{wvh, wvl, xh, xl, vth, vtl, D_MODEL, S_LEN, D_MODEL, S_LEN / BN};
    proj_fused_kernel<<<768, blk, GEMM_SMEM_BYTES>>>(sq, sk, sv);

    // scores = Q @ K^T -> fp32 P  [S, S]
    gemm_main<<<dim3(S_LEN / BN, S_LEN / BM), blk, GEMM_SMEM_BYTES>>>(
        qh, ql, kh, kl, P, nullptr, nullptr, S_LEN, S_LEN, D_MODEL);

    // softmax rows (single pass, row-in-registers), emits fp32 P + bf16 hi/lo
    softmax_rows_kernel<<<S_LEN, 256>>>(P, pph, ppl, S_LEN);

    // Vs = P @ (V^T)^T -> fp32  [S, D]
    gemm_main<<<dim3(D_MODEL / BN, S_LEN / BM), blk, GEMM_SMEM_BYTES>>>(
        pph, ppl, vth, vtl, Vs, nullptr, nullptr, S_LEN, D_MODEL, S_LEN);
}

// round 14
// speedup vs baseline: 1.0231x; 1.0110x over previous
#include <cuda_runtime.h>
#include <cuda_bf16.h>
#include <math.h>
#include <cstdint>

#define S_LEN 4096
#define D_MODEL 1024

// ============================ PTX helpers (sm_80-class only) ===============
__device__ __forceinline__ uint32_t smem_u32(const void* p) {
    uint32_t a;
    asm("{ .reg .u64 t; cvta.to.shared.u64 t, %1; cvt.u32.u64 %0, t; }"
        : "=r"(a) : "l"(p));
    return a;
}

__device__ __forceinline__ void cp_async16(uint32_t smem_addr, const void* gptr) {
    asm volatile("cp.async.cg.shared.global [%0], [%1], 16;"
                 :: "r"(smem_addr), "l"(gptr));
}
#define CP_COMMIT() asm volatile("cp.async.commit_group;" ::: "memory")
template<int N> __device__ __forceinline__ void cp_wait() {
    asm volatile("cp.async.wait_group %0;" :: "n"(N) : "memory");
}

__device__ __forceinline__ void ldmatrix_x4(uint32_t* r, uint32_t addr) {
    asm volatile("ldmatrix.sync.aligned.m8n8.x4.shared.b16 {%0,%1,%2,%3}, [%4];"
        : "=r"(r[0]), "=r"(r[1]), "=r"(r[2]), "=r"(r[3]) : "r"(addr));
}
// x4 variant loading TWO n8 B-tiles (both k-halves each) in one instruction.
__device__ __forceinline__ void ldmatrix_x4_b(uint32_t* r0, uint32_t* r1,
                                              uint32_t addr) {
    asm volatile("ldmatrix.sync.aligned.m8n8.x4.shared.b16 {%0,%1,%2,%3}, [%4];"
        : "=r"(r0[0]), "=r"(r0[1]), "=r"(r1[0]), "=r"(r1[1]) : "r"(addr));
}
__device__ __forceinline__ void mma_bf16(float* d, const uint32_t* a,
                                         const uint32_t* b) {
    asm volatile(
      "mma.sync.aligned.m16n8k16.row.col.f32.bf16.bf16.f32 "
      "{%0,%1,%2,%3}, {%4,%5,%6,%7}, {%8,%9}, {%0,%1,%2,%3};"
      : "+f"(d[0]), "+f"(d[1]), "+f"(d[2]), "+f"(d[3])
      : "r"(a[0]), "r"(a[1]), "r"(a[2]), "r"(a[3]), "r"(b[0]), "r"(b[1]));
}

// ============================ scratch (no allocs) ==========================
__device__ __nv_bfloat16 g_x_hi[S_LEN * D_MODEL],  g_x_lo[S_LEN * D_MODEL];
__device__ __nv_bfloat16 g_Wq_hi[D_MODEL * D_MODEL], g_Wq_lo[D_MODEL * D_MODEL];
__device__ __nv_bfloat16 g_Wk_hi[D_MODEL * D_MODEL], g_Wk_lo[D_MODEL * D_MODEL];
__device__ __nv_bfloat16 g_Wv_hi[D_MODEL * D_MODEL], g_Wv_lo[D_MODEL * D_MODEL];
__device__ __nv_bfloat16 g_Q_hi[S_LEN * D_MODEL],  g_Q_lo[S_LEN * D_MODEL];
__device__ __nv_bfloat16 g_K_hi[S_LEN * D_MODEL],  g_K_lo[S_LEN * D_MODEL];
__device__ __nv_bfloat16 g_VT_hi[D_MODEL * S_LEN], g_VT_lo[D_MODEL * S_LEN];
__device__ __nv_bfloat16 g_P_hi[(size_t)S_LEN * S_LEN];
__device__ __nv_bfloat16 g_P_lo[(size_t)S_LEN * S_LEN];
__device__ float g_Pscratch[(size_t)S_LEN * S_LEN];  // fallback

// ============================ fused split kernel ===========================
#define N_X  (S_LEN * D_MODEL)
#define N_W  (D_MODEL * D_MODEL)
__global__ void split_all_kernel(const float* __restrict__ x,
                                 const float* __restrict__ Wq,
                                 const float* __restrict__ Wk,
                                 const float* __restrict__ Wv,
                                 __nv_bfloat16* __restrict__ xh,  __nv_bfloat16* __restrict__ xl,
                                 __nv_bfloat16* __restrict__ wqh, __nv_bfloat16* __restrict__ wql,
                                 __nv_bfloat16* __restrict__ wkh, __nv_bfloat16* __restrict__ wkl,
                                 __nv_bfloat16* __restrict__ wvh, __nv_bfloat16* __restrict__ wvl)
{
    const int v = blockIdx.x * blockDim.x + threadIdx.x;   // float4 index
    const int NV_X = N_X / 4, NV_W = N_W / 4;
    const float* src; __nv_bfloat16* hi; __nv_bfloat16* lo; int idx;
    if (v < NV_X)                 { src = x;  hi = xh;  lo = xl;  idx = v; }
    else if (v < NV_X + NV_W)     { src = Wq; hi = wqh; lo = wql; idx = v - NV_X; }
    else if (v < NV_X + 2 * NV_W) { src = Wk; hi = wkh; lo = wkl; idx = v - NV_X - NV_W; }
    else if (v < NV_X + 3 * NV_W) { src = Wv; hi = wvh; lo = wvl; idx = v - NV_X - 2 * NV_W; }
    else return;

    float4 f = reinterpret_cast<const float4*>(src)[idx];
    __nv_bfloat162 h0, h1, l0, l1;
    h0.x = __float2bfloat16(f.x); l0.x = __float2bfloat16(f.x - __bfloat162float(h0.x));
    h0.y = __float2bfloat16(f.y); l0.y = __float2bfloat16(f.y - __bfloat162float(h0.y));
    h1.x = __float2bfloat16(f.z); l1.x = __float2bfloat16(f.z - __bfloat162float(h1.x));
    h1.y = __float2bfloat16(f.w); l1.y = __float2bfloat16(f.w - __bfloat162float(h1.y));
    reinterpret_cast<__nv_bfloat162*>(hi)[idx * 2 + 0] = h0;
    reinterpret_cast<__nv_bfloat162*>(hi)[idx * 2 + 1] = h1;
    reinterpret_cast<__nv_bfloat162*>(lo)[idx * 2 + 0] = l0;
    reinterpret_cast<__nv_bfloat162*>(lo)[idx * 2 + 1] = l1;
}

// ============================ mma.sync GEMM ================================
// C[M,N] = A[M,K] @ B[N,K]^T, bf16x3 split, fp32 accum.
// 128 threads = 4 warps (2x2), warp tile 64x64.
// XOR-swizzled smem, 3-stage cp.async pipeline, ONE __syncthreads per chunk.
// Fragment loads issued ONE MMA PHASE EARLY.
#define BM 128
#define BN 128
#define BK 32
#define NTHREADS 128
#define TILE_BYTES (BM * BK * 2)          // 8192
#define STAGE_BYTES (4 * TILE_BYTES)      // 32768 (Ah,Al,Bh,Bl)
#define NSTAGE 3
#define GEMM_SMEM_BYTES (NSTAGE * STAGE_BYTES)  // 98304

// byte offset of 16B granule (r, c16) within a tile
#define SWZ_OFF(r, c16) ((uint32_t)((r) * 64 + (((c16) ^ (((r) >> 1) & 3)) * 16)))

__device__ __forceinline__ void load_tile(
    const __nv_bfloat16* __restrict__ g, int row0, int K, int k0,
    uint32_t sm_base_bytes, int tid)
{
    #pragma unroll
    for (int j = 0; j < 4; j++) {
        int v = tid + j * NTHREADS;     // 0..511 16B granules
        int r = v >> 2;                 // 0..127
        int c16 = v & 3;                // 0..3
        const void* gp = g + (size_t)(row0 + r) * K + k0 + c16 * 8;
        cp_async16(sm_base_bytes + SWZ_OFF(r, c16), gp);
    }
}

__device__ __forceinline__ void gemm_core(
    const __nv_bfloat16* __restrict__ A_hi, const __nv_bfloat16* __restrict__ A_lo,
    const __nv_bfloat16* __restrict__ B_hi, const __nv_bfloat16* __restrict__ B_lo,
    float* __restrict__ Cf,
    __nv_bfloat16* __restrict__ C_hi, __nv_bfloat16* __restrict__ C_lo,
    int M, int N, int K, int m0, int n0)
{
    extern __shared__ __nv_bfloat16 smem[];
    const int tid = threadIdx.x;
    const int wid = tid >> 5;
    const int lane = tid & 31;
    const int wm = wid >> 1;            // 0..1 (64-row band)
    const int wn = wid & 1;             // 0..1 (64-col band)

    const uint32_t sb = smem_u32(smem);
    auto tile_base = [&](int s, int t) -> uint32_t {
        return sb + (uint32_t)(s * STAGE_BYTES + t * TILE_BYTES);
    };
    auto load_chunk = [&](int slot, int k0) {
        load_tile(A_hi, m0, K, k0, tile_base(slot, 0), tid);
        load_tile(A_lo, m0, K, k0, tile_base(slot, 1), tid);
        load_tile(B_hi, n0, K, k0, tile_base(slot, 2), tid);
        load_tile(B_lo, n0, K, k0, tile_base(slot, 3), tid);
    };

    float acc[4][8][4];                 // 128 regs: 4 mt x 8 nt x 4
    #pragma unroll
    for (int a = 0; a < 4; a++)
        #pragma unroll
        for (int b = 0; b < 8; b++)
            #pragma unroll
            for (int c = 0; c < 4; c++) acc[a][b][c] = 0.f;

    const int nch = K / BK;

    // prologue: stages 0 and 1 in flight
    load_chunk(0, 0);  CP_COMMIT();
    load_chunk(1, BK); CP_COMMIT();

    // lane-address components
    const int a_r = wm * 64 + (lane & 15);
    const int a_g = lane >> 4;                       // 0..1
    const int b_r = wn * 64 + (lane & 7) + ((lane >> 4) << 3);
    const int b_g = (lane >> 3) & 1;

    for (int i = 0; i < nch; i++) {
        if (i == nch - 1) cp_wait<0>(); else cp_wait<1>();
        __syncthreads();   // also guarantees stage (i+2)%3 fully consumed

        if (i + 2 < nch) {
            load_chunk((i + 2) % NSTAGE, (i + 2) * BK);
            CP_COMMIT();
        }

        const int s = i % NSTAGE;
        const uint32_t aAh = tile_base(s, 0);
        const uint32_t aAl = tile_base(s, 1);
        const uint32_t aBh = tile_base(s, 2);
        const uint32_t aBl = tile_base(s, 3);

        const int ac0 = a_g,     bc0 = b_g;          // ks=0 granule cols
        const int ac1 = 2 + a_g, bc1 = 2 + b_g;      // ks=1 granule cols

        uint32_t ah0[4][4], ah1[4][4], bh0[8][2], bh1[8][2];
        uint32_t al[4][4], bl[8][2];

        // --- loads staged one MMA phase ahead of their consumers ---

        // L: ah0, bh0 (exposed: chunk start, right after barrier)
        #pragma unroll
        for (int mt = 0; mt < 4; mt++)
            ldmatrix_x4(ah0[mt], aAh + SWZ_OFF(a_r + mt * 16, ac0));
        #pragma unroll
        for (int np = 0; np < 4; np++)
            ldmatrix_x4_b(bh0[np * 2], bh0[np * 2 + 1],
                          aBh + SWZ_OFF(b_r + np * 16, bc0));
        // L: al (ks0) — completes under hh0
        #pragma unroll
        for (int mt = 0; mt < 4; mt++)
            ldmatrix_x4(al[mt], aAl + SWZ_OFF(a_r + mt * 16, ac0));

        // MMA hh0
        #pragma unroll
        for (int mt = 0; mt < 4; mt++)
            #pragma unroll
            for (int nt = 0; nt < 8; nt++)
                mma_bf16(acc[mt][nt], ah0[mt], bh0[nt]);

        // L: bl (ks0) — completes under lh0
        #pragma unroll
        for (int np = 0; np < 4; np++)
            ldmatrix_x4_b(bl[np * 2], bl[np * 2 + 1],
                          aBl + SWZ_OFF(b_r + np * 16, bc0));

        // MMA lh0 (al x bh0; both die after)
        #pragma unroll
        for (int mt = 0; mt < 4; mt++)
            #pragma unroll
            for (int nt = 0; nt < 8; nt++)
                mma_bf16(acc[mt][nt], al[mt], bh0[nt]);

        // L: ah1, bh1 — complete under hl0
        #pragma unroll
        for (int mt = 0; mt < 4; mt++)
            ldmatrix_x4(ah1[mt], aAh + SWZ_OFF(a_r + mt * 16, ac1));
        #pragma unroll
        for (int np = 0; np < 4; np++)
            ldmatrix_x4_b(bh1[np * 2], bh1[np * 2 + 1],
                          aBh + SWZ_OFF(b_r + np * 16, bc1));

        // MMA hl0 (ah0 x bl; both die after)
        #pragma unroll
        for (int mt = 0; mt < 4; mt++)
            #pragma unroll
            for (int nt = 0; nt < 8; nt++)
                mma_bf16(acc[mt][nt], ah0[mt], bl[nt]);

        // L: al (ks1) — completes under hh1
        #pragma unroll
        for (int mt = 0; mt < 4; mt++)
            ldmatrix_x4(al[mt], aAl + SWZ_OFF(a_r + mt * 16, ac1));

        // MMA hh1
        #pragma unroll
        for (int mt = 0; mt < 4; mt++)
            #pragma unroll
            for (int nt = 0; nt < 8; nt++)
                mma_bf16(acc[mt][nt], ah1[mt], bh1[nt]);

        // L: bl (ks1) — completes under lh1
        #pragma unroll
        for (int np = 0; np < 4; np++)
            ldmatrix_x4_b(bl[np * 2], bl[np * 2 + 1],
                          aBl + SWZ_OFF(b_r + np * 16, bc1));

        // MMA lh1
        #pragma unroll
        for (int mt = 0; mt < 4; mt++)
            #pragma unroll
            for (int nt = 0; nt < 8; nt++)
                mma_bf16(acc[mt][nt], al[mt], bh1[nt]);

        // MMA hl1
        #pragma unroll
        for (int mt = 0; mt < 4; mt++)
            #pragma unroll
            for (int nt = 0; nt < 8; nt++)
                mma_bf16(acc[mt][nt], ah1[mt], bl[nt]);
    }

    // epilogue
    const int tr = lane >> 2;           // 0..7
    const int tc = (lane & 3) * 2;      // 0,2,4,6
    const int r0 = m0 + wm * 64;
    const int c0 = n0 + wn * 64;

    #pragma unroll
    for (int mt = 0; mt < 4; mt++) {
        #pragma unroll
        for (int nt = 0; nt < 8; nt++) {
            const float* d = acc[mt][nt];
            const int row = r0 + mt * 16 + tr;
            const int col = c0 + nt * 8 + tc;
            if (Cf != nullptr) {
                *reinterpret_cast<float2*>(&Cf[(size_t)row * N + col]) =
                    make_float2(d[0], d[1]);
                *reinterpret_cast<float2*>(&Cf[(size_t)(row + 8) * N + col]) =
                    make_float2(d[2], d[3]);
            } else {
                #pragma unroll
                for (int e = 0; e < 2; e++) {
                    const int rr = row + e * 8;
                    __nv_bfloat162 h2, l2;
                    {
                        float v = d[e * 2 + 0];
                        __nv_bfloat16 h = __float2bfloat16(v);
                        h2.x = h; l2.x = __float2bfloat16(v - __bfloat162float(h));
                    }
                    {
                        float v = d[e * 2 + 1];
                        __nv_bfloat16 h = __float2bfloat16(v);
                        h2.y = h; l2.y = __float2bfloat16(v - __bfloat162float(h));
                    }
                    *reinterpret_cast<__nv_bfloat162*>(
                        &C_hi[(size_t)rr * N + col]) = h2;
                    *reinterpret_cast<__nv_bfloat162*>(
                        &C_lo[(size_t)rr * N + col]) = l2;
                }
            }
        }
    }
}

// ============================ GEMM kernels =================================
__global__ void __launch_bounds__(NTHREADS)
gemm_main(const __nv_bfloat16* __restrict__ A_hi, const __nv_bfloat16* __restrict__ A_lo,
          const __nv_bfloat16* __restrict__ B_hi, const __nv_bfloat16* __restrict__ B_lo,
          float* __restrict__ Cf,
          __nv_bfloat16* __restrict__ C_hi, __nv_bfloat16* __restrict__ C_lo,
          int M, int N, int K)
{
    gemm_core(A_hi, A_lo, B_hi, B_lo, Cf, C_hi, C_lo, M, N, K,
              blockIdx.y * BM, blockIdx.x * BN);
}

struct ProjSet {
    const __nv_bfloat16 *Ah, *Al, *Bh, *Bl;
    __nv_bfloat16 *Ch, *Cl;
    int M, N, K, gx;
};

// Q and K projections fused in one 512-CTA launch (256 CTAs each).
__global__ void __launch_bounds__(NTHREADS)
proj_qk_kernel(ProjSet s0, ProjSet s1)
{
    const int b = blockIdx.x;
    ProjSet s = (b < 256) ? s0 : s1;
    const int r = b & 255;
    const int bx = r % s.gx;
    const int by = r / s.gx;
    gemm_core(s.Ah, s.Al, s.Bh, s.Bl, nullptr, s.Ch, s.Cl,
              s.M, s.N, s.K, by * BM, bx * BN);
}

// ============================ softmax (single pass, row in registers) ======
__global__ void __launch_bounds__(256)
softmax_rows_kernel(float* __restrict__ P,
                    __nv_bfloat16* __restrict__ Phi,
                    __nv_bfloat16* __restrict__ Plo, int n)
{
    float4* p4 = reinterpret_cast<float4*>(P + (size_t)blockIdx.x * n);
    __nv_bfloat162* ph2 = reinterpret_cast<__nv_bfloat162*>(Phi + (size_t)blockIdx.x * n);
    __nv_bfloat162* pl2 = reinterpret_cast<__nv_bfloat162*>(Plo + (size_t)blockIdx.x * n);
    __shared__ float red[256];
    const int t = threadIdx.x;
    const float scale = 1.0f / 32.0f;

    float4 v[4];
    float sum = 0.f;
    #pragma unroll
    for (int j = 0; j < 4; j++) {
        float4 f = p4[t + j * 256];
        f.x = __expf(f.x * scale);
        f.y = __expf(f.y * scale);
        f.z = __expf(f.z * scale);
        f.w = __expf(f.w * scale);
        v[j] = f;
        sum += (f.x + f.y) + (f.z + f.w);
    }

    red[t] = sum;
    __syncthreads();
    for (int s = 128; s > 0; s >>= 1) {
        if (t < s) red[t] += red[t + s];
        __syncthreads();
    }
    const float inv = 1.f / red[0];

    #pragma unroll
    for (int j = 0; j < 4; j++) {
        float4 f = v[j];
        f.x *= inv; f.y *= inv; f.z *= inv; f.w *= inv;
        p4[t + j * 256] = f;
        __nv_bfloat162 h0, h1, l0, l1;
        h0.x = __float2bfloat16(f.x); l0.x = __float2bfloat16(f.x - __bfloat162float(h0.x));
        h0.y = __float2bfloat16(f.y); l0.y = __float2bfloat16(f.y - __bfloat162float(h0.y));
        h1.x = __float2bfloat16(f.z); l1.x = __float2bfloat16(f.z - __bfloat162float(h1.x));
        h1.y = __float2bfloat16(f.w); l1.y = __float2bfloat16(f.w - __bfloat162float(h1.y));
        const int i = t + j * 256;
        ph2[i * 2 + 0] = h0; ph2[i * 2 + 1] = h1;
        pl2[i * 2 + 0] = l0; pl2[i * 2 + 1] = l1;
    }
}

// ============================ launch =======================================
extern "C" void kernel_launch(void* const* d_in, const int* in_sizes, int n_in,
                              void* d_out, int out_size)
{
    const float* x  = (const float*)d_in[0];
    const float* Wq = (const float*)d_in[1];
    const float* Wk = (const float*)d_in[2];
    const float* Wv = (const float*)d_in[3];
    float* out = (float*)d_out;

    __nv_bfloat16 *xh, *xl, *wqh, *wql, *wkh, *wkl, *wvh, *wvl;
    __nv_bfloat16 *qh, *ql, *kh, *kl, *vth, *vtl, *pph, *ppl;
    float* dPs;
    cudaGetSymbolAddress((void**)&xh,  g_x_hi);  cudaGetSymbolAddress((void**)&xl,  g_x_lo);
    cudaGetSymbolAddress((void**)&wqh, g_Wq_hi); cudaGetSymbolAddress((void**)&wql, g_Wq_lo);
    cudaGetSymbolAddress((void**)&wkh, g_Wk_hi); cudaGetSymbolAddress((void**)&wkl, g_Wk_lo);
    cudaGetSymbolAddress((void**)&wvh, g_Wv_hi); cudaGetSymbolAddress((void**)&wvl, g_Wv_lo);
    cudaGetSymbolAddress((void**)&qh,  g_Q_hi);  cudaGetSymbolAddress((void**)&ql,  g_Q_lo);
    cudaGetSymbolAddress((void**)&kh,  g_K_hi);  cudaGetSymbolAddress((void**)&kl,  g_K_lo);
    cudaGetSymbolAddress((void**)&vth, g_VT_hi); cudaGetSymbolAddress((void**)&vtl, g_VT_lo);
    cudaGetSymbolAddress((void**)&pph, g_P_hi);  cudaGetSymbolAddress((void**)&ppl, g_P_lo);
    cudaGetSymbolAddress((void**)&dPs, g_Pscratch);

    float* Vs = out;
    const long long need = (long long)S_LEN * D_MODEL + (long long)S_LEN * S_LEN;
    float* P = (out_size >= need) ? (out + (size_t)S_LEN * D_MODEL) : dPs;

    cudaFuncSetAttribute(gemm_main,
                         cudaFuncAttributeMaxDynamicSharedMemorySize,
                         GEMM_SMEM_BYTES);
    cudaFuncSetAttribute(proj_qk_kernel,
                         cudaFuncAttributeMaxDynamicSharedMemorySize,
                         GEMM_SMEM_BYTES);

    // One-time host resources (created on the first, uncaptured call).
    static cudaStream_t s_side = nullptr;
    static cudaEvent_t e_split = nullptr, e_v = nullptr;
    if (s_side == nullptr) {
        cudaStreamCreateWithFlags(&s_side, cudaStreamNonBlocking);
        cudaEventCreateWithFlags(&e_split, cudaEventDisableTiming);
        cudaEventCreateWithFlags(&e_v, cudaEventDisableTiming);
    }

    // fused split: x + Wq + Wk + Wv, float4-vectorized (main stream)
    {
        int total_vec = (N_X + 3 * N_W) / 4;
        split_all_kernel<<<(total_vec + 255) / 256, 256>>>(
            x, Wq, Wk, Wv, xh, xl, wqh, wql, wkh, wkl, wvh, wvl);
    }
    cudaEventRecord(e_split, 0);

    dim3 blk(NTHREADS);

    // side stream: V^T = Wv @ x^T  [D,S] — overlaps with QK proj + scores
    cudaStreamWaitEvent(s_side, e_split, 0);
    gemm_main<<<dim3(S_LEN / BN, D_MODEL / BM), blk, GEMM_SMEM_BYTES, s_side>>>(
        wvh, wvl, xh, xl, nullptr, vth, vtl, D_MODEL, S_LEN, D_MODEL);
    cudaEventRecord(e_v, s_side);

    // main stream: Q and K projections (512 CTAs)
    ProjSet sq{xh, xl, wqh, wql, qh, ql, S_LEN, D_MODEL, D_MODEL, D_MODEL / BN};
    ProjSet sk{xh, xl, wkh, wkl, kh, kl, S_LEN, D_MODEL, D_MODEL, D_MODEL / BN};
    proj_qk_kernel<<<512, blk, GEMM_SMEM_BYTES>>>(sq, sk);

    // scores = Q @ K^T -> fp32 P  [S, S]  (tail wave backfilled by V proj)
    gemm_main<<<dim3(S_LEN / BN, S_LEN / BM), blk, GEMM_SMEM_BYTES>>>(
        qh, ql, kh, kl, P, nullptr, nullptr, S_LEN, S_LEN, D_MODEL);

    // softmax rows (single pass, row-in-registers), emits fp32 P + bf16 hi/lo
    softmax_rows_kernel<<<S_LEN, 256>>>(P, pph, ppl, S_LEN);

    // join: PV needs V^T
    cudaStreamWaitEvent(0, e_v, 0);

    // Vs = P @ (V^T)^T -> fp32  [S, D]
    gemm_main<<<dim3(D_MODEL / BN, S_LEN / BM), blk, GEMM_SMEM_BYTES>>>(
        pph, ppl, vth, vtl, Vs, nullptr, nullptr, S_LEN, D_MODEL, S_LEN);
}